// round 10
// baseline (speedup 1.0000x reference)
#include <cuda_runtime.h>
#include <cstdint>

// PatchEmbed permute: x[16,64,256,256] f32 -> out[16, 64*64, 64*4*4]
// out[n, wp, hp, c, pi, pj] = x[n, c, hp*4+pi, wp*4+pj]
// pj (4 floats) => float4 units. Per (n, hp): transpose M[cp=256][wp=64]
// of float4 where cp = c*4+pi.
//   input  f4 idx = ((n*64 + c)*256 + hp*4 + pi)*64 + wp
//   output f4 idx = ((n*64 + wp)*64 + hp)*256 + cp
//
// R10: maximize WRITE burst length. Tile = full cp range (256) x 8 wp ->
// each (wp,hp) output row is written as one 4KB fully-contiguous burst
// (8x longer than all prior variants' 512B), cutting HBM write row
// activations. Reads become 128B-line granular (4 full aligned lines per
// warp request -- zero waste). Padded smem [256][9]f4 = 36KB; 512 thr at
// __launch_bounds__(512,4) -> 64 warps/SM. Both smem phases conflict-free
// (load: banks 4*col; store: banks 4*cp, distinct per 8-lane phase).

#define N_ 16
#define C_ 64
#define HP_ 64
#define WP_ 64
#define CP_ 256            // C_*4
#define WPT_ 8             // wp per tile
#define THREADS 512
#define NDATA    (N_ * C_ * 256 * 256)     // data size in floats

__global__ __launch_bounds__(THREADS, 4)
void patch_permute_kernel(const float4* __restrict__ in, float4* __restrict__ out,
                          int tail_count) {
    __shared__ float4 tile[CP_][WPT_ + 1];   // 36 KB, pad 9 -> conflict-free

    const int wpb = blockIdx.x;    // 0..7   (wp in [wpb*8, wpb*8+8))
    const int hp  = blockIdx.y;    // 0..63
    const int n   = blockIdx.z;    // 0..15
    const int tid = threadIdx.x;

    // ---- fused tail write (ori_shape = 16,64,256,256), one block only ----
    if (wpb == 0 && hp == 0 && n == 0 && tid < 4 && tid < tail_count) {
        const float vals[4] = {16.0f, 64.0f, 256.0f, 256.0f};
        ((float*)out)[NDATA + tid] = vals[tid];
    }

    // ---- load: per warp 4 full 128B lines (1KB-aligned row bases) ----
#pragma unroll
    for (int i = 0; i < (CP_ * WPT_) / THREADS; i++) {   // 4 iters
        int idx = i * THREADS + tid;
        int cp  = idx >> 3;          // 0..255
        int col = idx & 7;           // 0..7
        int c   = cp >> 2;
        int pi  = cp & 3;
        int in_idx = ((n * C_ + c) * 256 + hp * 4 + pi) * WP_ + wpb * WPT_ + col;
        tile[cp][col] = in[in_idx];
    }
    __syncthreads();

    // ---- store: 4KB contiguous per (wp,hp); 512B per warp request ----
#pragma unroll
    for (int i = 0; i < (CP_ * WPT_) / THREADS; i++) {   // 4 iters
        int idx = i * THREADS + tid;
        int wpl = idx >> 8;          // 0..7
        int cp  = idx & 255;         // 0..255
        int wp  = wpb * WPT_ + wpl;
        int out_idx = ((n * WP_ + wp) * HP_ + hp) * CP_ + cp;
        out[out_idx] = tile[cp][wpl];
    }
}

extern "C" void kernel_launch(void* const* d_in, const int* in_sizes, int n_in,
                              void* d_out, int out_size) {
    (void)in_sizes; (void)n_in;
    const float4* in  = (const float4*)d_in[0];
    float4*       out = (float4*)d_out;

    int tail_count = out_size > NDATA ? (out_size - NDATA) : 0;

    dim3 grid(WP_ / WPT_, HP_, N_);   // 8 x 64 x 16 = 8192 blocks
    patch_permute_kernel<<<grid, THREADS>>>(in, out, tail_count);
}

// round 11
// speedup vs baseline: 1.0051x; 1.0051x over previous
#include <cuda_runtime.h>
#include <cstdint>

// PatchEmbed permute: x[16,64,256,256] f32 -> out[16, 64*64, 64*4*4]
// out[n, wp, hp, c, pi, pj] = x[n, c, hp*4+pi, wp*4+pj]
// pj (4 floats) => float4 units. Per (n, hp): transpose M[cp=256][wp=64]
// of float4 where cp = c*4+pi.
//   input  f4 idx = ((n*64 + c)*256 + hp*4 + pi)*64 + wp   (contiguous in wp)
//   output f4 idx = ((n*64 + wp)*64 + hp)*256 + cp          (contiguous in cp)
//
// FINAL (R11): best-measured config (R7/R8: 256 thr, 16KB tile, plain
// LDG/STG, 64 warps/SM) -- 75.4us kernel = 7.1 TB/s = ~89% of spec HBM on a
// 50/50 mixed R/W stream. Seven structural variants (cp.async, 2/3-stage
// pipelines, barrier scopes, warp-autonomous tiles, 4KB write bursts) all
// measured neutral: this is the mixed-stream HBM ceiling. Only change vs R8:
// hp is the fastest grid dim (concurrent CTAs stream sequential input rows).

#define N_ 16
#define C_ 64
#define HP_ 64
#define WP_ 64
#define CP_ 256            // C_*4
#define CPT_ 16            // cp rows per tile
#define THREADS 256
#define NDATA    (N_ * C_ * 256 * 256)     // data size in floats

__global__ __launch_bounds__(THREADS, 8)
void patch_permute_kernel(const float4* __restrict__ in, float4* __restrict__ out,
                          int tail_count) {
    __shared__ float4 tile[CPT_][WP_];   // 16 KB, XOR-swizzled

    const int hp  = blockIdx.x;    // 0..63  (fastest: sequential input rows)
    const int cpt = blockIdx.y;    // 0..15  (cp in [cpt*16, cpt*16+16))
    const int n   = blockIdx.z;    // 0..15
    const int tid = threadIdx.x;

    // ---- fused tail write (ori_shape = 16,64,256,256), one block only ----
    if (cpt == 0 && hp == 0 && n == 0 && tid < 4 && tid < tail_count) {
        const float vals[4] = {16.0f, 64.0f, 256.0f, 256.0f};
        ((float*)out)[NDATA + tid] = vals[tid];
    }

    // ---- load: coalesced over wp (512B per warp), swizzled smem store ----
#pragma unroll
    for (int i = 0; i < (CPT_ * WP_) / THREADS; i++) {   // 4 iters
        int idx = i * THREADS + tid;
        int cpl = idx >> 6;          // 0..15
        int wp  = idx & 63;          // 0..63
        int cp  = cpt * CPT_ + cpl;
        int c   = cp >> 2;
        int pi  = cp & 3;
        int in_idx = ((n * C_ + c) * 256 + hp * 4 + pi) * WP_ + wp;
        tile[cpl][wp ^ (cpl & 7)] = in[in_idx];
    }
    __syncthreads();

    // ---- store: coalesced over cp, swizzled smem read ----
#pragma unroll
    for (int i = 0; i < (CPT_ * WP_) / THREADS; i++) {   // 4 iters
        int idx = i * THREADS + tid;
        int wp  = idx >> 4;          // 0..63
        int cpl = idx & 15;          // 0..15
        int cp  = cpt * CPT_ + cpl;
        int out_idx = ((n * WP_ + wp) * HP_ + hp) * CP_ + cp;
        out[out_idx] = tile[cpl][wp ^ (cpl & 7)];
    }
}

extern "C" void kernel_launch(void* const* d_in, const int* in_sizes, int n_in,
                              void* d_out, int out_size) {
    (void)in_sizes; (void)n_in;
    const float4* in  = (const float4*)d_in[0];
    float4*       out = (float4*)d_out;

    int tail_count = out_size > NDATA ? (out_size - NDATA) : 0;

    dim3 grid(HP_, CP_ / CPT_, N_);   // 64 x 16 x 16 = 16384 blocks
    patch_permute_kernel<<<grid, THREADS>>>(in, out, tail_count);
}